// round 10
// baseline (speedup 1.0000x reference)
#include <cuda_runtime.h>
#include <cuda_fp16.h>
#include <math.h>

#define NN 50000
#define EE 800000
#define GG 1024
#define DD 64
#define DIN 9
#define CAP 96                    // bucket capacity per node (max in-deg ~40)
#define NBLK ((NN + 255) / 256)   // 196

// ---------------- scratch (static device globals; no allocation) ------------
__device__ int      g_pos[NN];         // fill cursor; after fill = in-degree
__device__ float    g_dinv[NN];        // rsqrt(deg+1)
__device__ int      g_srcs[NN * CAP];  // bucketed CSR: sources per destination
__device__ __align__(16) __half g_featA[NN * DD];  // feature ping (dinv-scaled)
__device__ __align__(16) __half g_featB[NN * DD];  // feature pong
__device__ float    g_agg[NN * DIN];   // layer-0 aggregation output (fp32)
__device__ unsigned g_gmax[GG * DD];
__device__ float    g_gsum[GG * DD];
__device__ int      g_gcnt[GG];

// ---------------- setup -----------------------------------------------------
__global__ void k_init() {
    int i = blockIdx.x * blockDim.x + threadIdx.x;   // grid covers 65536
    if (i < NN) g_pos[i] = 0;
    if (i < GG * DD) { g_gmax[i] = 0u; g_gsum[i] = 0.f; }
    if (i < GG) g_gcnt[i] = 0;
}

// bucket scatter: 2 edges per thread
__global__ void k_fill(const int* __restrict__ ei) {
    int e2 = (blockIdx.x * blockDim.x + threadIdx.x) * 2;
    if (e2 < EE) {
        int2 s = *(const int2*)(ei + e2);            // sources
        int2 d = *(const int2*)(ei + EE + e2);       // destinations
        int p0 = atomicAdd(&g_pos[d.x], 1);
        int p1 = atomicAdd(&g_pos[d.y], 1);
        if (p0 < CAP) g_srcs[d.x * CAP + p0] = s.x;
        if (p1 < CAP) g_srcs[d.y * CAP + p1] = s.y;
    }
}

__global__ void k_dinv(const int* __restrict__ batch) {
    int i = blockIdx.x * blockDim.x + threadIdx.x;
    if (i < NN) {
        g_dinv[i] = rsqrtf((float)(g_pos[i] + 1));
        atomicAdd(&g_gcnt[batch[i]], 1);
    }
}

// ---------------- layer-0 aggregation over raw 9-dim x ----------------------
// out[v] = dinv[v] * ( sum_s dinv[s]*x[s] + dinv[v]*x[v] )
__global__ void k_agg9(const float* __restrict__ x, float* __restrict__ out) {
    int w = (blockIdx.x * blockDim.x + threadIdx.x) >> 5;
    int lane = threadIdx.x & 31;
    if (w >= NN) return;
    int start = w * CAP, cnt = g_pos[w];
    float a = 0.f;
    for (int base = 0; base < cnt; base += 32) {
        int m = min(32, cnt - base);
        int sl = 0; float dl = 0.f;
        if (lane < m) { sl = g_srcs[start + base + lane]; dl = g_dinv[sl]; }
        for (int i = 0; i < m; i++) {
            int s    = __shfl_sync(0xffffffffu, sl, i);
            float ws = __shfl_sync(0xffffffffu, dl, i);
            if (lane < DIN) a += ws * x[s * DIN + lane];
        }
    }
    float di = g_dinv[w];
    if (lane < DIN) {
        a += di * x[w * DIN + lane];
        out[w * DIN + lane] = di * a;
    }
}

// ---------------- layer-0 GEMM (K=9): thread-per-node ------------------------
__global__ __launch_bounds__(256) void k_gemm9(const float* __restrict__ A,
        const float* __restrict__ W, const float* __restrict__ b,
        __half* __restrict__ fout) {
    __shared__ float Ws[DIN * DD];
    __shared__ float bs[DD];
    int tid = threadIdx.x;
    for (int i = tid; i < DIN * DD; i += 256) Ws[i] = W[i];
    if (tid < DD) bs[tid] = b[tid];
    __syncthreads();
    int node = blockIdx.x * 256 + tid;
    if (node >= NN) return;
    float a[DIN];
#pragma unroll
    for (int k = 0; k < DIN; k++) a[k] = A[node * DIN + k];
    float di = g_dinv[node];
    __half2* o = (__half2*)(fout + node * DD);
#pragma unroll
    for (int c = 0; c < DD; c += 2) {
        float a0 = bs[c], a1 = bs[c + 1];
#pragma unroll
        for (int k = 0; k < DIN; k++) {
            a0 = fmaf(a[k], Ws[k * DD + c],     a0);
            a1 = fmaf(a[k], Ws[k * DD + c + 1], a1);
        }
        o[c >> 1] = __floats2half2_rn(di * tanhf(a0), di * tanhf(a1));
    }
}

// ---------------- fused layer: aggregation + GEMM + epilogue -----------------
// fin holds fs[v] = dinv[v]*h[v].  agg[v] = dinv[v]*( sum_s fs[s] + fs[v] )
// then out = tanh(agg @ W + b); POOL=0 -> fout = dinv*out (fp16); POOL=1 -> pooling.
// Block = 256 threads, 64 nodes.  Agg: 8 warps x 8 nodes (quad-edge gather).
#define APAD 72   // padded row stride (floats), 16B-aligned
template <int POOL>
__global__ __launch_bounds__(256) void k_layer(const __half* __restrict__ fin,
        __half* __restrict__ fout, const float* __restrict__ W,
        const float* __restrict__ b, const int* __restrict__ batch) {
    __shared__ float As[DD * APAD];    // node-major: As[n*APAD + k]
    __shared__ float Ws[DD * DD];
    int tid = threadIdx.x, lane = tid & 31, wrp = tid >> 5;
    int grp = lane >> 3, sub = lane & 7;
    int node0 = blockIdx.x * DD;
    for (int i = tid; i < DD * DD; i += 256) Ws[i] = W[i];

    const uint4* __restrict__ F = (const uint4*)fin;   // node row = 8 uint4
    for (int r = 0; r < 8; r++) {
        int w = node0 + (wrp << 3) + r;
        int valid = (w < NN);
        int start = w * CAP;
        int cnt = valid ? g_pos[w] : 0;
        float acc[8];
#pragma unroll
        for (int j = 0; j < 8; j++) acc[j] = 0.f;

        for (int base = 0; base < cnt; base += 32) {
            int m = min(32, cnt - base);
            int sl = (lane < m) ? g_srcs[start + base + lane] : 0;
            for (int i = 0; i < m; i += 4) {
                int e = i + grp;
                int s = __shfl_sync(0xffffffffu, sl, e & 31);
                if (e < m) {
                    uint4 v = F[s * 8 + sub];
                    float2 f0 = __half22float2(*(const __half2*)&v.x);
                    float2 f1 = __half22float2(*(const __half2*)&v.y);
                    float2 f2 = __half22float2(*(const __half2*)&v.z);
                    float2 f3 = __half22float2(*(const __half2*)&v.w);
                    acc[0] += f0.x; acc[1] += f0.y;
                    acc[2] += f1.x; acc[3] += f1.y;
                    acc[4] += f2.x; acc[5] += f2.y;
                    acc[6] += f3.x; acc[7] += f3.y;
                }
            }
        }
#pragma unroll
        for (int j = 0; j < 8; j++) {
            acc[j] += __shfl_xor_sync(0xffffffffu, acc[j], 8);
            acc[j] += __shfl_xor_sync(0xffffffffu, acc[j], 16);
        }
        if (grp == 0) {                               // lanes 0..7 write node row
            if (valid) {
                uint4 v = F[w * 8 + sub];             // self term fs[v]
                float2 f0 = __half22float2(*(const __half2*)&v.x);
                float2 f1 = __half22float2(*(const __half2*)&v.y);
                float2 f2 = __half22float2(*(const __half2*)&v.z);
                float2 f3 = __half22float2(*(const __half2*)&v.w);
                acc[0] += f0.x; acc[1] += f0.y;
                acc[2] += f1.x; acc[3] += f1.y;
                acc[4] += f2.x; acc[5] += f2.y;
                acc[6] += f3.x; acc[7] += f3.y;
                float di = g_dinv[w];
#pragma unroll
                for (int j = 0; j < 8; j++) acc[j] *= di;
            } else {
#pragma unroll
                for (int j = 0; j < 8; j++) acc[j] = 0.f;
            }
            float* ap = &As[((wrp << 3) + r) * APAD + (sub << 3)];
            *(float4*)(ap)     = make_float4(acc[0], acc[1], acc[2], acc[3]);
            *(float4*)(ap + 4) = make_float4(acc[4], acc[5], acc[6], acc[7]);
        }
    }
    __syncthreads();

    // ---- GEMM: 4 nodes x 4 cols per thread, k blocked by 4 ----
    int n0 = (tid >> 4) << 2;
    int c0 = (tid & 15) << 2;
    float4 bv = *(const float4*)(b + c0);
    float acc[4][4];
#pragma unroll
    for (int i = 0; i < 4; i++) {
        acc[i][0] = bv.x; acc[i][1] = bv.y; acc[i][2] = bv.z; acc[i][3] = bv.w;
    }
#pragma unroll
    for (int k4 = 0; k4 < DD; k4 += 4) {
        float4 a4[4];
#pragma unroll
        for (int i = 0; i < 4; i++) a4[i] = *(const float4*)&As[(n0 + i) * APAD + k4];
#pragma unroll
        for (int kk = 0; kk < 4; kk++) {
            float4 wv = *(const float4*)&Ws[(k4 + kk) * DD + c0];
            float ww[4] = {wv.x, wv.y, wv.z, wv.w};
#pragma unroll
            for (int i = 0; i < 4; i++) {
                float aa = ((const float*)&a4[i])[kk];
#pragma unroll
                for (int j = 0; j < 4; j++)
                    acc[i][j] = fmaf(aa, ww[j], acc[i][j]);
            }
        }
    }
#pragma unroll
    for (int i = 0; i < 4; i++) {
        int node = node0 + n0 + i;
        if (node >= NN) continue;
        float v[4];
#pragma unroll
        for (int j = 0; j < 4; j++) v[j] = tanhf(acc[i][j]);
        if (POOL) {
            int g = batch[node] * DD + c0;
#pragma unroll
            for (int j = 0; j < 4; j++) {
                float x = v[j];
                unsigned enc = (x >= 0.f) ? (__float_as_uint(x) | 0x80000000u)
                                          : ~__float_as_uint(x);
                atomicMax(&g_gmax[g + j], enc);
                atomicAdd(&g_gsum[g + j], x);
            }
        } else {
            float di = g_dinv[node];
            __half2* o = (__half2*)(fout + node * DD + c0);
            o[0] = __floats2half2_rn(di * v[0], di * v[1]);
            o[1] = __floats2half2_rn(di * v[2], di * v[3]);
        }
    }
}

// ---------------- readout ----------------------------------------------------
__global__ void k_out(const float* __restrict__ Wout, const float* __restrict__ bout,
                      float* __restrict__ out) {
    int g = blockIdx.x;
    int lane = threadIdx.x;
    float cnt = fmaxf((float)g_gcnt[g], 1.f);
    float s = 0.f;
    for (int f = lane; f < DD; f += 32) {
        unsigned e = g_gmax[g * DD + f];
        float mx = (e & 0x80000000u) ? __uint_as_float(e & 0x7FFFFFFFu)
                                     : __uint_as_float(~e);
        float mn = g_gsum[g * DD + f] / cnt;
        s += mx * Wout[f] + mn * Wout[DD + f];
    }
#pragma unroll
    for (int o = 16; o > 0; o >>= 1) s += __shfl_down_sync(0xFFFFFFFFu, s, o);
    if (lane == 0) out[g] = s + bout[0];
}

// ---------------- launch ----------------------------------------------------
extern "C" void kernel_launch(void* const* d_in, const int* in_sizes, int n_in,
                              void* d_out, int out_size) {
    const float* x     = (const float*)d_in[0];
    const int*   ei    = (const int*)d_in[1];
    const int*   batch = (const int*)d_in[2];
    const float* W0    = (const float*)d_in[3];
    const float* b0    = (const float*)d_in[4];
    const float* W1    = (const float*)d_in[5];
    const float* b1    = (const float*)d_in[6];
    const float* W2    = (const float*)d_in[7];
    const float* b2    = (const float*)d_in[8];
    const float* W3    = (const float*)d_in[9];
    const float* b3    = (const float*)d_in[10];
    const float* Wout  = (const float*)d_in[11];
    const float* bout  = (const float*)d_in[12];
    float* out = (float*)d_out;

    float* aggp;  __half *fA, *fB;
    cudaGetSymbolAddress((void**)&aggp, g_agg);
    cudaGetSymbolAddress((void**)&fA, g_featA);
    cudaGetSymbolAddress((void**)&fB, g_featB);

    const int EB2  = (EE / 2 + 255) / 256;    // 1563 (2 edges/thread)
    const int AGGB = (NN * 32 + 255) / 256;   // 6250 (warp per node)
    const int GB   = (NN + DD - 1) / DD;      // 782  (64-node tiles)

    k_init<<<256, 256>>>();
    k_fill<<<EB2, 256>>>(ei);
    k_dinv<<<NBLK, 256>>>(batch);

    // layer 0: aggregate raw 9-dim x, GEMM K=9 -> featA (dinv-scaled fp16)
    k_agg9<<<AGGB, 256>>>(x, aggp);
    k_gemm9<<<NBLK, 256>>>(aggp, W0, b0, fA);
    // fused layers 1..3 (double-buffered features)
    k_layer<0><<<GB, 256>>>(fA, fB, W1, b1, nullptr);
    k_layer<0><<<GB, 256>>>(fB, fA, W2, b2, nullptr);
    k_layer<1><<<GB, 256>>>(fA, nullptr, W3, b3, batch);

    k_out<<<GG, 32>>>(Wout, bout, out);
}

// round 11
// speedup vs baseline: 1.0015x; 1.0015x over previous
#include <cuda_runtime.h>
#include <cuda_fp16.h>
#include <math.h>

#define NN 50000
#define EE 800000
#define GG 1024
#define DD 64
#define DIN 9
#define CAP 96                    // bucket capacity per node (max in-deg ~40)
#define NBLK ((NN + 255) / 256)   // 196

// ---------------- scratch (static device globals; no allocation) ------------
__device__ int      g_pos[NN];         // fill cursor; after fill = in-degree
__device__ float    g_dinv[NN];        // rsqrt(deg+1)
__device__ int      g_srcs[NN * CAP];  // bucketed CSR: sources per destination
__device__ __align__(16) __half g_t[NN * DD];   // ts[v] = dinv[v]*(h@W)[v]
__device__ __align__(16) __half g_h[NN * DD];   // h[v] = tanh(conv)
__device__ unsigned g_gmax[GG * DD];
__device__ float    g_gsum[GG * DD];
__device__ int      g_gcnt[GG];

// ---------------- setup -----------------------------------------------------
__global__ void k_init() {
    int i = blockIdx.x * blockDim.x + threadIdx.x;   // grid covers 65536
    if (i < NN) g_pos[i] = 0;
    if (i < GG * DD) { g_gmax[i] = 0u; g_gsum[i] = 0.f; }
    if (i < GG) g_gcnt[i] = 0;
}

// bucket scatter: 2 edges per thread
__global__ void k_fill(const int* __restrict__ ei) {
    int e2 = (blockIdx.x * blockDim.x + threadIdx.x) * 2;
    if (e2 < EE) {
        int2 s = *(const int2*)(ei + e2);            // sources
        int2 d = *(const int2*)(ei + EE + e2);       // destinations
        int p0 = atomicAdd(&g_pos[d.x], 1);
        int p1 = atomicAdd(&g_pos[d.y], 1);
        if (p0 < CAP) g_srcs[d.x * CAP + p0] = s.x;
        if (p1 < CAP) g_srcs[d.y * CAP + p1] = s.y;
    }
}

__global__ void k_dinv(const int* __restrict__ batch) {
    int i = blockIdx.x * blockDim.x + threadIdx.x;
    if (i < NN) {
        g_dinv[i] = rsqrtf((float)(g_pos[i] + 1));
        atomicAdd(&g_gcnt[batch[i]], 1);
    }
}

// ---------------- layer-0 transform: t0 = dinv * (x @ W0), fp16 --------------
__global__ __launch_bounds__(256) void k_gemm9x(const float* __restrict__ x,
        const float* __restrict__ W, __half* __restrict__ tout) {
    __shared__ float Ws[DIN * DD];
    int tid = threadIdx.x;
    for (int i = tid; i < DIN * DD; i += 256) Ws[i] = W[i];
    __syncthreads();
    int node = blockIdx.x * 256 + tid;
    if (node >= NN) return;
    float a[DIN];
#pragma unroll
    for (int k = 0; k < DIN; k++) a[k] = x[node * DIN + k];
    float di = g_dinv[node];
    __half2* o = (__half2*)(tout + node * DD);
#pragma unroll
    for (int c = 0; c < DD; c += 2) {
        float a0 = 0.f, a1 = 0.f;
#pragma unroll
        for (int k = 0; k < DIN; k++) {
            a0 = fmaf(a[k], Ws[k * DD + c],     a0);
            a1 = fmaf(a[k], Ws[k * DD + c + 1], a1);
        }
        o[c >> 1] = __floats2half2_rn(di * a0, di * a1);
    }
}

// ---------------- aggregation + bias + tanh epilogue -------------------------
// tin holds ts[v] = dinv[v]*(hW)[v].
// h[v] = tanh( dinv[v]*( sum_s ts[s] + ts[v] ) + b )
// POOL=0: write h as fp16. POOL=1: fused max/sum pooling over h.
// Warp per node; quad-edge gather: 8 lanes/edge, one uint4 (8 halves) each.
template <int POOL>
__global__ void k_aggE(const __half* __restrict__ tin, __half* __restrict__ hout,
                       const float* __restrict__ b, const int* __restrict__ batch) {
    int w = (blockIdx.x * blockDim.x + threadIdx.x) >> 5;
    int lane = threadIdx.x & 31;
    if (w >= NN) return;
    int grp = lane >> 3;          // which edge within quad (0..3)
    int sub = lane & 7;           // dim-chunk (8 halves each)
    int start = w * CAP, cnt = g_pos[w];
    const uint4* __restrict__ F = (const uint4*)tin;   // node row = 8 uint4
    float acc[8];
#pragma unroll
    for (int j = 0; j < 8; j++) acc[j] = 0.f;

    for (int base = 0; base < cnt; base += 32) {
        int m = min(32, cnt - base);
        int sl = (lane < m) ? g_srcs[start + base + lane] : 0;
        for (int i = 0; i < m; i += 4) {
            int e = i + grp;
            int s = __shfl_sync(0xffffffffu, sl, e & 31);
            if (e < m) {
                uint4 v = F[s * 8 + sub];
                float2 f0 = __half22float2(*(const __half2*)&v.x);
                float2 f1 = __half22float2(*(const __half2*)&v.y);
                float2 f2 = __half22float2(*(const __half2*)&v.z);
                float2 f3 = __half22float2(*(const __half2*)&v.w);
                acc[0] += f0.x; acc[1] += f0.y;
                acc[2] += f1.x; acc[3] += f1.y;
                acc[4] += f2.x; acc[5] += f2.y;
                acc[6] += f3.x; acc[7] += f3.y;
            }
        }
    }
    // reduce across the 4 edge-groups
#pragma unroll
    for (int j = 0; j < 8; j++) {
        acc[j] += __shfl_xor_sync(0xffffffffu, acc[j], 8);
        acc[j] += __shfl_xor_sync(0xffffffffu, acc[j], 16);
    }
    if (grp == 0) {                                   // lanes 0..7 finish node
        uint4 v = F[w * 8 + sub];                     // self term ts[v]
        float2 f0 = __half22float2(*(const __half2*)&v.x);
        float2 f1 = __half22float2(*(const __half2*)&v.y);
        float2 f2 = __half22float2(*(const __half2*)&v.z);
        float2 f3 = __half22float2(*(const __half2*)&v.w);
        acc[0] += f0.x; acc[1] += f0.y;
        acc[2] += f1.x; acc[3] += f1.y;
        acc[4] += f2.x; acc[5] += f2.y;
        acc[6] += f3.x; acc[7] += f3.y;
        float di = g_dinv[w];
        float4 b0 = *(const float4*)(b + sub * 8);
        float4 b1 = *(const float4*)(b + sub * 8 + 4);
        float hv[8];
        hv[0] = tanhf(fmaf(di, acc[0], b0.x));
        hv[1] = tanhf(fmaf(di, acc[1], b0.y));
        hv[2] = tanhf(fmaf(di, acc[2], b0.z));
        hv[3] = tanhf(fmaf(di, acc[3], b0.w));
        hv[4] = tanhf(fmaf(di, acc[4], b1.x));
        hv[5] = tanhf(fmaf(di, acc[5], b1.y));
        hv[6] = tanhf(fmaf(di, acc[6], b1.z));
        hv[7] = tanhf(fmaf(di, acc[7], b1.w));
        if (POOL) {
            int g = batch[w] * DD + sub * 8;
#pragma unroll
            for (int j = 0; j < 8; j++) {
                float xv = hv[j];
                unsigned enc = (xv >= 0.f) ? (__float_as_uint(xv) | 0x80000000u)
                                           : ~__float_as_uint(xv);
                atomicMax(&g_gmax[g + j], enc);
                atomicAdd(&g_gsum[g + j], xv);
            }
        } else {
            uint4 o;
            *(__half2*)&o.x = __floats2half2_rn(hv[0], hv[1]);
            *(__half2*)&o.y = __floats2half2_rn(hv[2], hv[3]);
            *(__half2*)&o.z = __floats2half2_rn(hv[4], hv[5]);
            *(__half2*)&o.w = __floats2half2_rn(hv[6], hv[7]);
            ((uint4*)hout)[w * 8 + sub] = o;
        }
    }
}

// ---------------- K=64 GEMM on fp16 h: t = dinv * (h @ W), fp16 --------------
__global__ __launch_bounds__(256) void k_gemm64f(const __half* __restrict__ hin,
        const float* __restrict__ W, __half* __restrict__ tout) {
    __shared__ float As[DD][DD + 4];   // transposed tile: As[k][n]
    __shared__ float Ws[DD * DD];
    int tid = threadIdx.x;
    int node0 = blockIdx.x * DD;
    for (int i = tid; i < DD * DD; i += 256) Ws[i] = W[i];
    // load 64 nodes x 64 dims fp16 -> fp32 transposed (half2 granularity)
    const __half2* H = (const __half2*)hin;
    for (int i = tid; i < DD * 32; i += 256) {        // 2048 half2 per tile
        int n = i >> 5, kk = i & 31;
        int node = node0 + n;
        float2 f = (node < NN) ? __half22float2(H[node * 32 + kk])
                               : make_float2(0.f, 0.f);
        As[2 * kk][n]     = f.x;
        As[2 * kk + 1][n] = f.y;
    }
    __syncthreads();
    int n0 = (tid >> 4) << 2;
    int c0 = (tid & 15) << 2;
    float acc[4][4];
#pragma unroll
    for (int i = 0; i < 4; i++)
#pragma unroll
        for (int j = 0; j < 4; j++) acc[i][j] = 0.f;
#pragma unroll
    for (int k = 0; k < DD; k++) {
        float4 av = *(const float4*)&As[k][n0];
        float4 wv = *(const float4*)&Ws[k * DD + c0];
        float aa[4] = {av.x, av.y, av.z, av.w};
        float ww[4] = {wv.x, wv.y, wv.z, wv.w};
#pragma unroll
        for (int i = 0; i < 4; i++)
#pragma unroll
            for (int j = 0; j < 4; j++)
                acc[i][j] = fmaf(aa[i], ww[j], acc[i][j]);
    }
#pragma unroll
    for (int i = 0; i < 4; i++) {
        int node = node0 + n0 + i;
        if (node >= NN) continue;
        float di = g_dinv[node];
        __half2* o = (__half2*)(tout + node * DD + c0);
        o[0] = __floats2half2_rn(di * acc[i][0], di * acc[i][1]);
        o[1] = __floats2half2_rn(di * acc[i][2], di * acc[i][3]);
    }
}

// ---------------- readout ----------------------------------------------------
__global__ void k_out(const float* __restrict__ Wout, const float* __restrict__ bout,
                      float* __restrict__ out) {
    int g = blockIdx.x;
    int lane = threadIdx.x;
    float cnt = fmaxf((float)g_gcnt[g], 1.f);
    float s = 0.f;
    for (int f = lane; f < DD; f += 32) {
        unsigned e = g_gmax[g * DD + f];
        float mx = (e & 0x80000000u) ? __uint_as_float(e & 0x7FFFFFFFu)
                                     : __uint_as_float(~e);
        float mn = g_gsum[g * DD + f] / cnt;
        s += mx * Wout[f] + mn * Wout[DD + f];
    }
#pragma unroll
    for (int o = 16; o > 0; o >>= 1) s += __shfl_down_sync(0xFFFFFFFFu, s, o);
    if (lane == 0) out[g] = s + bout[0];
}

// ---------------- launch ----------------------------------------------------
extern "C" void kernel_launch(void* const* d_in, const int* in_sizes, int n_in,
                              void* d_out, int out_size) {
    const float* x     = (const float*)d_in[0];
    const int*   ei    = (const int*)d_in[1];
    const int*   batch = (const int*)d_in[2];
    const float* W0    = (const float*)d_in[3];
    const float* b0    = (const float*)d_in[4];
    const float* W1    = (const float*)d_in[5];
    const float* b1    = (const float*)d_in[6];
    const float* W2    = (const float*)d_in[7];
    const float* b2    = (const float*)d_in[8];
    const float* W3    = (const float*)d_in[9];
    const float* b3    = (const float*)d_in[10];
    const float* Wout  = (const float*)d_in[11];
    const float* bout  = (const float*)d_in[12];
    float* out = (float*)d_out;

    __half *tp, *hp;
    cudaGetSymbolAddress((void**)&tp, g_t);
    cudaGetSymbolAddress((void**)&hp, g_h);

    const int EB2  = (EE / 2 + 255) / 256;    // 1563 (2 edges/thread)
    const int AGGB = (NN * 32 + 255) / 256;   // 6250 (warp per node)
    const int GB   = (NN + DD - 1) / DD;      // 782  (64-node tiles)

    k_init<<<256, 256>>>();
    k_fill<<<EB2, 256>>>(ei);
    k_dinv<<<NBLK, 256>>>(batch);

    // transform-then-aggregate, all layers use the fast 64-dim gather
    k_gemm9x<<<NBLK, 256>>>(x, W0, tp);               // t0 = dinv*(x@W0)
    k_aggE<0><<<AGGB, 256>>>(tp, hp, b0, nullptr);    // h1
    k_gemm64f<<<GB, 256>>>(hp, W1, tp);               // t1 = dinv*(h1@W1)
    k_aggE<0><<<AGGB, 256>>>(tp, hp, b1, nullptr);    // h2
    k_gemm64f<<<GB, 256>>>(hp, W2, tp);               // t2
    k_aggE<0><<<AGGB, 256>>>(tp, hp, b2, nullptr);    // h3
    k_gemm64f<<<GB, 256>>>(hp, W3, tp);               // t3
    k_aggE<1><<<AGGB, 256>>>(tp, nullptr, b3, batch); // h4 + fused pooling

    k_out<<<GG, 32>>>(Wout, bout, out);
}

// round 12
// speedup vs baseline: 1.0228x; 1.0213x over previous
#include <cuda_runtime.h>
#include <cuda_fp16.h>
#include <math.h>

#define NN 50000
#define EE 800000
#define GG 1024
#define DD 64
#define DIN 9
#define CAP 96                    // bucket capacity per node (max in-deg ~40)
#define NBLK ((NN + 255) / 256)   // 196

// ---------------- scratch (static device globals; no allocation) ------------
__device__ int      g_pos[NN];         // fill cursor; after fill = in-degree
__device__ float    g_dinv[NN];        // rsqrt(deg+1)
__device__ int      g_srcs[NN * CAP];  // bucketed CSR (padded to mult of 8 w/ NN)
__device__ __align__(16) __half g_t[(NN + 1) * DD]; // ts[v]=dinv*(h@W); row NN = 0
__device__ __align__(16) __half g_h[NN * DD];       // h[v] = tanh(conv)
__device__ unsigned g_gmax[GG * DD];
__device__ float    g_gsum[GG * DD];
__device__ int      g_gcnt[GG];

// ---------------- setup -----------------------------------------------------
__global__ void k_init() {
    int i = blockIdx.x * blockDim.x + threadIdx.x;   // grid covers 65536
    if (i < NN) g_pos[i] = 0;
    if (i < GG * DD) { g_gmax[i] = 0u; g_gsum[i] = 0.f; }
    if (i < GG) g_gcnt[i] = 0;
    if (i < DD) g_t[NN * DD + i] = __float2half(0.f);   // dummy-node row
}

// bucket scatter: 2 edges per thread
__global__ void k_fill(const int* __restrict__ ei) {
    int e2 = (blockIdx.x * blockDim.x + threadIdx.x) * 2;
    if (e2 < EE) {
        int2 s = *(const int2*)(ei + e2);            // sources
        int2 d = *(const int2*)(ei + EE + e2);       // destinations
        int p0 = atomicAdd(&g_pos[d.x], 1);
        int p1 = atomicAdd(&g_pos[d.y], 1);
        if (p0 < CAP) g_srcs[d.x * CAP + p0] = s.x;
        if (p1 < CAP) g_srcs[d.y * CAP + p1] = s.y;
    }
}

// dinv + graph counts + pad each bucket to a multiple of 8 with dummy node NN
__global__ void k_dinv(const int* __restrict__ batch) {
    int i = blockIdx.x * blockDim.x + threadIdx.x;
    if (i < NN) {
        int c = min(g_pos[i], CAP);
        int cntp = (c + 7) & ~7;                     // <= CAP (CAP mult of 8)
        for (int j = c; j < cntp; j++) g_srcs[i * CAP + j] = NN;
        g_dinv[i] = rsqrtf((float)(g_pos[i] + 1));
        atomicAdd(&g_gcnt[batch[i]], 1);
    }
}

// ---------------- layer-0 transform: t0 = dinv * (x @ W0), fp16 --------------
// 4 threads per node, 16 columns each (occupancy fix: grid 782)
__global__ __launch_bounds__(256) void k_gemm9x(const float* __restrict__ x,
        const float* __restrict__ W, __half* __restrict__ tout) {
    __shared__ float Ws[DIN * DD];
    int tid = threadIdx.x;
    for (int i = tid; i < DIN * DD; i += 256) Ws[i] = W[i];
    __syncthreads();
    int idx = blockIdx.x * 256 + tid;
    int node = idx >> 2, q = idx & 3;
    if (node >= NN) return;
    float a[DIN];
#pragma unroll
    for (int k = 0; k < DIN; k++) a[k] = x[node * DIN + k];
    float di = g_dinv[node];
    int c0 = q * 16;
    __half2 o[8];
#pragma unroll
    for (int c = 0; c < 16; c += 2) {
        float a0 = 0.f, a1 = 0.f;
#pragma unroll
        for (int k = 0; k < DIN; k++) {
            a0 = fmaf(a[k], Ws[k * DD + c0 + c],     a0);
            a1 = fmaf(a[k], Ws[k * DD + c0 + c + 1], a1);
        }
        o[c >> 1] = __floats2half2_rn(di * a0, di * a1);
    }
    uint4* op = (uint4*)(tout + node * DD + c0);
    op[0] = *(uint4*)&o[0];
    op[1] = *(uint4*)&o[4];
}

// ---------------- aggregation + bias + tanh epilogue -------------------------
// tin holds ts[v] = dinv[v]*(hW)[v];  h[v] = tanh( dinv[v]*(sum_s ts[s] + ts[v]) + b )
// Warp per node. 8 lanes per edge-pair: buckets padded to mult of 8 -> no
// per-edge predicate; fp16 pair-add (hadd2) halves convert/add count.
template <int POOL>
__global__ void k_aggE(const __half* __restrict__ tin, __half* __restrict__ hout,
                       const float* __restrict__ b, const int* __restrict__ batch) {
    int w = (blockIdx.x * blockDim.x + threadIdx.x) >> 5;
    int lane = threadIdx.x & 31;
    if (w >= NN) return;
    int grp = lane >> 3;          // edge-pair slot within octet (0..3)
    int sub = lane & 7;           // dim-chunk (8 halves)
    int start = w * CAP;
    int c = min(g_pos[w], CAP);
    int cntp = (c + 7) & ~7;      // padded count (multiple of 8)
    const uint4* __restrict__ F = (const uint4*)tin;   // node row = 8 uint4
    float acc[8];
#pragma unroll
    for (int j = 0; j < 8; j++) acc[j] = 0.f;

    for (int base = 0; base < cntp; base += 32) {
        int m = min(32, cntp - base);                 // multiple of 8
        int sl = (lane < m) ? g_srcs[start + base + lane] : 0;
        for (int i = 0; i < m; i += 8) {
            int e = i + (grp << 1);
            int s0 = __shfl_sync(0xffffffffu, sl, e);
            int s1 = __shfl_sync(0xffffffffu, sl, e + 1);
            uint4 v0 = F[s0 * 8 + sub];
            uint4 v1 = F[s1 * 8 + sub];
            __half2 p0 = __hadd2(*(const __half2*)&v0.x, *(const __half2*)&v1.x);
            __half2 p1 = __hadd2(*(const __half2*)&v0.y, *(const __half2*)&v1.y);
            __half2 p2 = __hadd2(*(const __half2*)&v0.z, *(const __half2*)&v1.z);
            __half2 p3 = __hadd2(*(const __half2*)&v0.w, *(const __half2*)&v1.w);
            float2 f0 = __half22float2(p0), f1 = __half22float2(p1);
            float2 f2 = __half22float2(p2), f3 = __half22float2(p3);
            acc[0] += f0.x; acc[1] += f0.y;
            acc[2] += f1.x; acc[3] += f1.y;
            acc[4] += f2.x; acc[5] += f2.y;
            acc[6] += f3.x; acc[7] += f3.y;
        }
    }
    // reduce across the 4 pair-groups
#pragma unroll
    for (int j = 0; j < 8; j++) {
        acc[j] += __shfl_xor_sync(0xffffffffu, acc[j], 8);
        acc[j] += __shfl_xor_sync(0xffffffffu, acc[j], 16);
    }
    if (grp == 0) {                                   // lanes 0..7 finish node
        uint4 v = F[w * 8 + sub];                     // self term ts[v]
        float2 f0 = __half22float2(*(const __half2*)&v.x);
        float2 f1 = __half22float2(*(const __half2*)&v.y);
        float2 f2 = __half22float2(*(const __half2*)&v.z);
        float2 f3 = __half22float2(*(const __half2*)&v.w);
        acc[0] += f0.x; acc[1] += f0.y;
        acc[2] += f1.x; acc[3] += f1.y;
        acc[4] += f2.x; acc[5] += f2.y;
        acc[6] += f3.x; acc[7] += f3.y;
        float di = g_dinv[w];
        float4 b0 = *(const float4*)(b + sub * 8);
        float4 b1 = *(const float4*)(b + sub * 8 + 4);
        float hv[8];
        hv[0] = tanhf(fmaf(di, acc[0], b0.x));
        hv[1] = tanhf(fmaf(di, acc[1], b0.y));
        hv[2] = tanhf(fmaf(di, acc[2], b0.z));
        hv[3] = tanhf(fmaf(di, acc[3], b0.w));
        hv[4] = tanhf(fmaf(di, acc[4], b1.x));
        hv[5] = tanhf(fmaf(di, acc[5], b1.y));
        hv[6] = tanhf(fmaf(di, acc[6], b1.z));
        hv[7] = tanhf(fmaf(di, acc[7], b1.w));
        if (POOL) {
            int g = batch[w] * DD + sub * 8;
#pragma unroll
            for (int j = 0; j < 8; j++) {
                float xv = hv[j];
                unsigned enc = (xv >= 0.f) ? (__float_as_uint(xv) | 0x80000000u)
                                           : ~__float_as_uint(xv);
                atomicMax(&g_gmax[g + j], enc);
                atomicAdd(&g_gsum[g + j], xv);
            }
        } else {
            uint4 o;
            *(__half2*)&o.x = __floats2half2_rn(hv[0], hv[1]);
            *(__half2*)&o.y = __floats2half2_rn(hv[2], hv[3]);
            *(__half2*)&o.z = __floats2half2_rn(hv[4], hv[5]);
            *(__half2*)&o.w = __floats2half2_rn(hv[6], hv[7]);
            ((uint4*)hout)[w * 8 + sub] = o;
        }
    }
}

// ---------------- K=64 GEMM on fp16 h: t = dinv * (h @ W), fp16 --------------
// Node-major smem tile (conflict-free float2 stores, broadcast float4 reads)
#define APAD 72
__global__ __launch_bounds__(256) void k_gemm64f(const __half* __restrict__ hin,
        const float* __restrict__ W, __half* __restrict__ tout) {
    __shared__ float As[DD * APAD];    // As[n*APAD + k]
    __shared__ float Ws[DD * DD];
    int tid = threadIdx.x;
    int node0 = blockIdx.x * DD;
    for (int i = tid; i < DD * DD; i += 256) Ws[i] = W[i];
    const __half2* H = (const __half2*)hin;
    for (int i = tid; i < DD * 32; i += 256) {        // 2048 half2 per tile
        int n = i >> 5, kk = i & 31;
        int node = node0 + n;
        float2 f = (node < NN) ? __half22float2(H[node * 32 + kk])
                               : make_float2(0.f, 0.f);
        *(float2*)&As[n * APAD + 2 * kk] = f;
    }
    __syncthreads();
    int n0 = (tid >> 4) << 2;
    int c0 = (tid & 15) << 2;
    float acc[4][4];
#pragma unroll
    for (int i = 0; i < 4; i++)
#pragma unroll
        for (int j = 0; j < 4; j++) acc[i][j] = 0.f;
#pragma unroll
    for (int k4 = 0; k4 < DD; k4 += 4) {
        float4 a4[4];
#pragma unroll
        for (int i = 0; i < 4; i++) a4[i] = *(const float4*)&As[(n0 + i) * APAD + k4];
#pragma unroll
        for (int kk = 0; kk < 4; kk++) {
            float4 wv = *(const float4*)&Ws[(k4 + kk) * DD + c0];
            float ww[4] = {wv.x, wv.y, wv.z, wv.w};
#pragma unroll
            for (int i = 0; i < 4; i++) {
                float aa = ((const float*)&a4[i])[kk];
#pragma unroll
                for (int j = 0; j < 4; j++)
                    acc[i][j] = fmaf(aa, ww[j], acc[i][j]);
            }
        }
    }
#pragma unroll
    for (int i = 0; i < 4; i++) {
        int node = node0 + n0 + i;
        if (node >= NN) continue;
        float di = g_dinv[node];
        __half2* o = (__half2*)(tout + node * DD + c0);
        o[0] = __floats2half2_rn(di * acc[i][0], di * acc[i][1]);
        o[1] = __floats2half2_rn(di * acc[i][2], di * acc[i][3]);
    }
}

// ---------------- readout ----------------------------------------------------
__global__ void k_out(const float* __restrict__ Wout, const float* __restrict__ bout,
                      float* __restrict__ out) {
    int g = blockIdx.x;
    int lane = threadIdx.x;
    float cnt = fmaxf((float)g_gcnt[g], 1.f);
    float s = 0.f;
    for (int f = lane; f < DD; f += 32) {
        unsigned e = g_gmax[g * DD + f];
        float mx = (e & 0x80000000u) ? __uint_as_float(e & 0x7FFFFFFFu)
                                     : __uint_as_float(~e);
        float mn = g_gsum[g * DD + f] / cnt;
        s += mx * Wout[f] + mn * Wout[DD + f];
    }
#pragma unroll
    for (int o = 16; o > 0; o >>= 1) s += __shfl_down_sync(0xFFFFFFFFu, s, o);
    if (lane == 0) out[g] = s + bout[0];
}

// ---------------- launch ----------------------------------------------------
extern "C" void kernel_launch(void* const* d_in, const int* in_sizes, int n_in,
                              void* d_out, int out_size) {
    const float* x     = (const float*)d_in[0];
    const int*   ei    = (const int*)d_in[1];
    const int*   batch = (const int*)d_in[2];
    const float* W0    = (const float*)d_in[3];
    const float* b0    = (const float*)d_in[4];
    const float* W1    = (const float*)d_in[5];
    const float* b1    = (const float*)d_in[6];
    const float* W2    = (const float*)d_in[7];
    const float* b2    = (const float*)d_in[8];
    const float* W3    = (const float*)d_in[9];
    const float* b3    = (const float*)d_in[10];
    const float* Wout  = (const float*)d_in[11];
    const float* bout  = (const float*)d_in[12];
    float* out = (float*)d_out;

    __half *tp, *hp;
    cudaGetSymbolAddress((void**)&tp, g_t);
    cudaGetSymbolAddress((void**)&hp, g_h);

    const int EB2  = (EE / 2 + 255) / 256;    // 1563 (2 edges/thread)
    const int AGGB = (NN * 32 + 255) / 256;   // 6250 (warp per node)
    const int GB   = (NN + DD - 1) / DD;      // 782  (64-node tiles)
    const int G9   = (NN * 4 + 255) / 256;    // 782  (4 threads/node)

    k_init<<<256, 256>>>();
    k_fill<<<EB2, 256>>>(ei);
    k_dinv<<<NBLK, 256>>>(batch);

    // transform-then-aggregate; all aggregations use the padded octet gather
    k_gemm9x<<<G9, 256>>>(x, W0, tp);                 // t0 = dinv*(x@W0)
    k_aggE<0><<<AGGB, 256>>>(tp, hp, b0, nullptr);    // h1
    k_gemm64f<<<GB, 256>>>(hp, W1, tp);               // t1 = dinv*(h1@W1)
    k_aggE<0><<<AGGB, 256>>>(tp, hp, b1, nullptr);    // h2
    k_gemm64f<<<GB, 256>>>(hp, W2, tp);               // t2
    k_aggE<0><<<AGGB, 256>>>(tp, hp, b2, nullptr);    // h3
    k_gemm64f<<<GB, 256>>>(hp, W3, tp);               // t3
    k_aggE<1><<<AGGB, 256>>>(tp, nullptr, b3, batch); // h4 + fused pooling

    k_out<<<GG, 32>>>(Wout, bout, out);
}

// round 13
// speedup vs baseline: 1.2758x; 1.2474x over previous
#include <cuda_runtime.h>
#include <cuda_fp16.h>
#include <mma.h>
#include <math.h>

using namespace nvcuda;

#define NN 50000
#define NP 50048                  // padded to multiple of 128 (tile size)
#define EE 800000
#define GG 1024
#define DD 64
#define DIN 9
#define CAP 96                    // bucket capacity per node (max in-deg ~40)
#define NBLK ((NN + 255) / 256)   // 196
#define GTB  (NP / 128)           // 391 tensor-GEMM blocks

// ---------------- scratch (static device globals; no allocation) ------------
__device__ int      g_pos[NN];         // fill cursor; after fill = in-degree
__device__ float    g_dinv[NN];        // rsqrt(deg+1)
__device__ int      g_srcs[NN * CAP];  // bucketed CSR (padded to mult of 8 w/ NN)
__device__ __align__(16) __half g_t[NP * DD];  // ts[v]=dinv*(h@W); pad rows stay 0
__device__ __align__(16) __half g_h[NP * DD];  // h[v]=tanh(conv);  pad rows stay 0
__device__ unsigned g_gmax[GG * DD];
__device__ float    g_gsum[GG * DD];
__device__ int      g_gcnt[GG];

// ---------------- setup -----------------------------------------------------
__global__ void k_init() {
    int i = blockIdx.x * blockDim.x + threadIdx.x;   // grid covers 65536
    if (i < NN) g_pos[i] = 0;
    if (i < GG * DD) { g_gmax[i] = 0u; g_gsum[i] = 0.f; }
    if (i < GG) g_gcnt[i] = 0;
}

// bucket scatter: 2 edges per thread
__global__ void k_fill(const int* __restrict__ ei) {
    int e2 = (blockIdx.x * blockDim.x + threadIdx.x) * 2;
    if (e2 < EE) {
        int2 s = *(const int2*)(ei + e2);            // sources
        int2 d = *(const int2*)(ei + EE + e2);       // destinations
        int p0 = atomicAdd(&g_pos[d.x], 1);
        int p1 = atomicAdd(&g_pos[d.y], 1);
        if (p0 < CAP) g_srcs[d.x * CAP + p0] = s.x;
        if (p1 < CAP) g_srcs[d.y * CAP + p1] = s.y;
    }
}

// dinv + graph counts + pad each bucket to a multiple of 8 with dummy node NN
// (dummy row NN of g_t lies in the static-zero pad region, never written)
__global__ void k_dinv(const int* __restrict__ batch) {
    int i = blockIdx.x * blockDim.x + threadIdx.x;
    if (i < NN) {
        int c = min(g_pos[i], CAP);
        int cntp = (c + 7) & ~7;                     // <= CAP (CAP mult of 8)
        for (int j = c; j < cntp; j++) g_srcs[i * CAP + j] = NN;
        g_dinv[i] = rsqrtf((float)(g_pos[i] + 1));
        atomicAdd(&g_gcnt[batch[i]], 1);
    }
}

// ---------------- tensor-core GEMM, layers 1-3: t = dinv * (h @ W) ----------
// Block = 256 thr (8 warps) = 128 nodes. A from global fp16, W fp32->fp16 smem.
__global__ __launch_bounds__(256) void k_gemmTC(const __half* __restrict__ A,
        const float* __restrict__ W, __half* __restrict__ tout) {
    __shared__ __half Wh[DD * 72];     // B: row-major k x n, ld 72
    __shared__ float  Os[128 * 72];    // fp32 staging, ld 72
    int tid = threadIdx.x, wid = tid >> 5;
    for (int i = tid; i < DD * DD; i += 256) {
        int k = i >> 6, n = i & 63;
        Wh[k * 72 + n] = __float2half(W[i]);
    }
    __syncthreads();
    int node0 = blockIdx.x * 128;
    const __half* Ap = A + (node0 + wid * 16) * DD;

    wmma::fragment<wmma::accumulator, 16, 16, 16, float> c[4];
#pragma unroll
    for (int n = 0; n < 4; n++) wmma::fill_fragment(c[n], 0.f);
#pragma unroll
    for (int k = 0; k < 4; k++) {
        wmma::fragment<wmma::matrix_a, 16, 16, 16, __half, wmma::row_major> a;
        wmma::load_matrix_sync(a, Ap + k * 16, DD);
#pragma unroll
        for (int n = 0; n < 4; n++) {
            wmma::fragment<wmma::matrix_b, 16, 16, 16, __half, wmma::row_major> b;
            wmma::load_matrix_sync(b, Wh + k * 16 * 72 + n * 16, 72);
            wmma::mma_sync(c[n], a, b, c[n]);
        }
    }
#pragma unroll
    for (int n = 0; n < 4; n++)
        wmma::store_matrix_sync(Os + wid * 16 * 72 + n * 16, c[n], 72,
                                wmma::mem_row_major);
    __syncthreads();
    // epilogue: scale by dinv, cvt fp16, vector store
    for (int i = tid; i < 128 * 8; i += 256) {       // 8-col chunks
        int r = i >> 3, ch = i & 7;
        int node = node0 + r;
        if (node >= NN) continue;
        float di = g_dinv[node];
        const float* src = Os + r * 72 + ch * 8;
        __half2 h0 = __floats2half2_rn(di * src[0], di * src[1]);
        __half2 h1 = __floats2half2_rn(di * src[2], di * src[3]);
        __half2 h2 = __floats2half2_rn(di * src[4], di * src[5]);
        __half2 h3 = __floats2half2_rn(di * src[6], di * src[7]);
        uint4 o;
        o.x = *(unsigned*)&h0; o.y = *(unsigned*)&h1;
        o.z = *(unsigned*)&h2; o.w = *(unsigned*)&h3;
        *(uint4*)(tout + node * DD + ch * 8) = o;
    }
}

// ---------------- tensor-core GEMM, layer 0: t0 = dinv * (x @ W0) -----------
// K = 9 padded to 16; A staged fp32->fp16 in smem.
__global__ __launch_bounds__(256) void k_gemmTC9(const float* __restrict__ x,
        const float* __restrict__ W, __half* __restrict__ tout) {
    __shared__ __half Wh[16 * 72];
    __shared__ __half Ax[128 * 24];    // 128 nodes x 16 (pad), ld 24
    __shared__ float  Os[128 * 72];
    int tid = threadIdx.x, wid = tid >> 5;
    for (int i = tid; i < 16 * DD; i += 256) {
        int k = i >> 6, n = i & 63;
        Wh[k * 72 + n] = (k < DIN) ? __float2half(W[k * DD + n])
                                   : __float2half(0.f);
    }
    int node0 = blockIdx.x * 128;
    for (int i = tid; i < 128 * 16; i += 256) {
        int r = i >> 4, k = i & 15;
        int node = node0 + r;
        float v = (node < NN && k < DIN) ? x[node * DIN + k] : 0.f;
        Ax[r * 24 + k] = __float2half(v);
    }
    __syncthreads();

    wmma::fragment<wmma::accumulator, 16, 16, 16, float> c[4];
#pragma unroll
    for (int n = 0; n < 4; n++) wmma::fill_fragment(c[n], 0.f);
    wmma::fragment<wmma::matrix_a, 16, 16, 16, __half, wmma::row_major> a;
    wmma::load_matrix_sync(a, Ax + wid * 16 * 24, 24);
#pragma unroll
    for (int n = 0; n < 4; n++) {
        wmma::fragment<wmma::matrix_b, 16, 16, 16, __half, wmma::row_major> b;
        wmma::load_matrix_sync(b, Wh + n * 16, 72);
        wmma::mma_sync(c[n], a, b, c[n]);
    }
#pragma unroll
    for (int n = 0; n < 4; n++)
        wmma::store_matrix_sync(Os + wid * 16 * 72 + n * 16, c[n], 72,
                                wmma::mem_row_major);
    __syncthreads();
    for (int i = tid; i < 128 * 8; i += 256) {
        int r = i >> 3, ch = i & 7;
        int node = node0 + r;
        if (node >= NN) continue;
        float di = g_dinv[node];
        const float* src = Os + r * 72 + ch * 8;
        __half2 h0 = __floats2half2_rn(di * src[0], di * src[1]);
        __half2 h1 = __floats2half2_rn(di * src[2], di * src[3]);
        __half2 h2 = __floats2half2_rn(di * src[4], di * src[5]);
        __half2 h3 = __floats2half2_rn(di * src[6], di * src[7]);
        uint4 o;
        o.x = *(unsigned*)&h0; o.y = *(unsigned*)&h1;
        o.z = *(unsigned*)&h2; o.w = *(unsigned*)&h3;
        *(uint4*)(tout + node * DD + ch * 8) = o;
    }
}

// ---------------- aggregation + bias + tanh epilogue -------------------------
// tin holds ts[v] = dinv[v]*(hW)[v];  h[v] = tanh( dinv[v]*(sum_s ts[s] + ts[v]) + b )
template <int POOL>
__global__ void k_aggE(const __half* __restrict__ tin, __half* __restrict__ hout,
                       const float* __restrict__ b, const int* __restrict__ batch) {
    int w = (blockIdx.x * blockDim.x + threadIdx.x) >> 5;
    int lane = threadIdx.x & 31;
    if (w >= NN) return;
    int grp = lane >> 3;          // edge-pair slot within octet (0..3)
    int sub = lane & 7;           // dim-chunk (8 halves)
    int start = w * CAP;
    int c = min(g_pos[w], CAP);
    int cntp = (c + 7) & ~7;      // padded count (multiple of 8)
    const uint4* __restrict__ F = (const uint4*)tin;   // node row = 8 uint4
    float acc[8];
#pragma unroll
    for (int j = 0; j < 8; j++) acc[j] = 0.f;

    for (int base = 0; base < cntp; base += 32) {
        int m = min(32, cntp - base);                 // multiple of 8
        int sl = (lane < m) ? g_srcs[start + base + lane] : 0;
        for (int i = 0; i < m; i += 8) {
            int e = i + (grp << 1);
            int s0 = __shfl_sync(0xffffffffu, sl, e);
            int s1 = __shfl_sync(0xffffffffu, sl, e + 1);
            uint4 v0 = F[s0 * 8 + sub];
            uint4 v1 = F[s1 * 8 + sub];
            __half2 p0 = __hadd2(*(const __half2*)&v0.x, *(const __half2*)&v1.x);
            __half2 p1 = __hadd2(*(const __half2*)&v0.y, *(const __half2*)&v1.y);
            __half2 p2 = __hadd2(*(const __half2*)&v0.z, *(const __half2*)&v1.z);
            __half2 p3 = __hadd2(*(const __half2*)&v0.w, *(const __half2*)&v1.w);
            float2 f0 = __half22float2(p0), f1 = __half22float2(p1);
            float2 f2 = __half22float2(p2), f3 = __half22float2(p3);
            acc[0] += f0.x; acc[1] += f0.y;
            acc[2] += f1.x; acc[3] += f1.y;
            acc[4] += f2.x; acc[5] += f2.y;
            acc[6] += f3.x; acc[7] += f3.y;
        }
    }
#pragma unroll
    for (int j = 0; j < 8; j++) {
        acc[j] += __shfl_xor_sync(0xffffffffu, acc[j], 8);
        acc[j] += __shfl_xor_sync(0xffffffffu, acc[j], 16);
    }
    if (grp == 0) {                                   // lanes 0..7 finish node
        uint4 v = F[w * 8 + sub];                     // self term ts[v]
        float2 f0 = __half22float2(*(const __half2*)&v.x);
        float2 f1 = __half22float2(*(const __half2*)&v.y);
        float2 f2 = __half22float2(*(const __half2*)&v.z);
        float2 f3 = __half22float2(*(const __half2*)&v.w);
        acc[0] += f0.x; acc[1] += f0.y;
        acc[2] += f1.x; acc[3] += f1.y;
        acc[4] += f2.x; acc[5] += f2.y;
        acc[6] += f3.x; acc[7] += f3.y;
        float di = g_dinv[w];
        float4 b0 = *(const float4*)(b + sub * 8);
        float4 b1 = *(const float4*)(b + sub * 8 + 4);
        float hv[8];
        hv[0] = tanhf(fmaf(di, acc[0], b0.x));
        hv[1] = tanhf(fmaf(di, acc[1], b0.y));
        hv[2] = tanhf(fmaf(di, acc[2], b0.z));
        hv[3] = tanhf(fmaf(di, acc[3], b0.w));
        hv[4] = tanhf(fmaf(di, acc[4], b1.x));
        hv[5] = tanhf(fmaf(di, acc[5], b1.y));
        hv[6] = tanhf(fmaf(di, acc[6], b1.z));
        hv[7] = tanhf(fmaf(di, acc[7], b1.w));
        if (POOL) {
            int g = batch[w] * DD + sub * 8;
#pragma unroll
            for (int j = 0; j < 8; j++) {
                float xv = hv[j];
                unsigned enc = (xv >= 0.f) ? (__float_as_uint(xv) | 0x80000000u)
                                           : ~__float_as_uint(xv);
                atomicMax(&g_gmax[g + j], enc);
                atomicAdd(&g_gsum[g + j], xv);
            }
        } else {
            uint4 o;
            *(__half2*)&o.x = __floats2half2_rn(hv[0], hv[1]);
            *(__half2*)&o.y = __floats2half2_rn(hv[2], hv[3]);
            *(__half2*)&o.z = __floats2half2_rn(hv[4], hv[5]);
            *(__half2*)&o.w = __floats2half2_rn(hv[6], hv[7]);
            ((uint4*)hout)[w * 8 + sub] = o;
        }
    }
}

// ---------------- readout ----------------------------------------------------
__global__ void k_out(const float* __restrict__ Wout, const float* __restrict__ bout,
                      float* __restrict__ out) {
    int g = blockIdx.x;
    int lane = threadIdx.x;
    float cnt = fmaxf((float)g_gcnt[g], 1.f);
    float s = 0.f;
    for (int f = lane; f < DD; f += 32) {
        unsigned e = g_gmax[g * DD + f];
        float mx = (e & 0x80000000u) ? __uint_as_float(e & 0x7FFFFFFFu)
                                     : __uint_as_float(~e);
        float mn = g_gsum[g * DD + f] / cnt;
        s += mx * Wout[f] + mn * Wout[DD + f];
    }
#pragma unroll
    for (int o = 16; o > 0; o >>= 1) s += __shfl_down_sync(0xFFFFFFFFu, s, o);
    if (lane == 0) out[g] = s + bout[0];
}

// ---------------- launch ----------------------------------------------------
extern "C" void kernel_launch(void* const* d_in, const int* in_sizes, int n_in,
                              void* d_out, int out_size) {
    const float* x     = (const float*)d_in[0];
    const int*   ei    = (const int*)d_in[1];
    const int*   batch = (const int*)d_in[2];
    const float* W0    = (const float*)d_in[3];
    const float* b0    = (const float*)d_in[4];
    const float* W1    = (const float*)d_in[5];
    const float* b1    = (const float*)d_in[6];
    const float* W2    = (const float*)d_in[7];
    const float* b2    = (const float*)d_in[8];
    const float* W3    = (const float*)d_in[9];
    const float* b3    = (const float*)d_in[10];
    const float* Wout  = (const float*)d_in[11];
    const float* bout  = (const float*)d_in[12];
    float* out = (float*)d_out;

    __half *tp, *hp;
    cudaGetSymbolAddress((void**)&tp, g_t);
    cudaGetSymbolAddress((void**)&hp, g_h);

    const int EB2  = (EE / 2 + 255) / 256;    // 1563 (2 edges/thread)
    const int AGGB = (NN * 32 + 255) / 256;   // 6250 (warp per node)

    k_init<<<256, 256>>>();
    k_fill<<<EB2, 256>>>(ei);
    k_dinv<<<NBLK, 256>>>(batch);

    // transform (tensor cores) then aggregate (octet gather)
    k_gemmTC9<<<GTB, 256>>>(x, W0, tp);               // t0 = dinv*(x@W0)
    k_aggE<0><<<AGGB, 256>>>(tp, hp, b0, nullptr);    // h1
    k_gemmTC<<<GTB, 256>>>(hp, W1, tp);               // t1 = dinv*(h1@W1)
    k_aggE<0><<<AGGB, 256>>>(tp, hp, b1, nullptr);    // h2
    k_gemmTC<<<GTB, 256>>>(hp, W2, tp);               // t2
    k_aggE<0><<<AGGB, 256>>>(tp, hp, b2, nullptr);    // h3
    k_gemmTC<<<GTB, 256>>>(hp, W3, tp);               // t3
    k_aggE<1><<<AGGB, 256>>>(tp, nullptr, b3, batch); // h4 + fused pooling

    k_out<<<GG, 32>>>(Wout, bout, out);
}